// round 5
// baseline (speedup 1.0000x reference)
#include <cuda_runtime.h>
#include <climits>

#define NB 32
#define H 512
#define W 512
#define C 3
#define OUT 400
#define THRESH 0.7f

#define BPB 16                      // bounds blocks per batch
#define ROWS_PER_BLK (H / BPB)      // 32
#define TB 256

// Per-block partial bbox: rmin, rmax, cmin, cmax. Plain-stored every launch.
__device__ int g_part[NB * BPB][4];

__global__ void bounds_kernel(const float* __restrict__ tensor) {
    int blk  = blockIdx.x;
    int b    = blk / BPB;
    int rb   = blk % BPB;
    int row0 = rb * ROWS_PER_BLK;

    const float4* base =
        (const float4*)(tensor + ((size_t)b * H + row0) * W);

    int rmin = INT_MAX, rmax = -1, cmin = INT_MAX, cmax = -1;

    const int NV = ROWS_PER_BLK * (W / 4);  // 4096 float4s
    for (int j = threadIdx.x; j < NV; j += TB) {
        float4 v = base[j];
        int r = j >> 7;
        int c = (j & 127) << 2;
        bool any = false;
        if (v.x > THRESH) { any = true; cmin = min(cmin, c    ); cmax = max(cmax, c    ); }
        if (v.y > THRESH) { any = true; cmin = min(cmin, c + 1); cmax = max(cmax, c + 1); }
        if (v.z > THRESH) { any = true; cmin = min(cmin, c + 2); cmax = max(cmax, c + 2); }
        if (v.w > THRESH) { any = true; cmin = min(cmin, c + 3); cmax = max(cmax, c + 3); }
        if (any) {
            int rr = row0 + r;
            rmin = min(rmin, rr);
            rmax = max(rmax, rr);
        }
    }

    #pragma unroll
    for (int o = 16; o > 0; o >>= 1) {
        rmin = min(rmin, __shfl_xor_sync(0xFFFFFFFFu, rmin, o));
        rmax = max(rmax, __shfl_xor_sync(0xFFFFFFFFu, rmax, o));
        cmin = min(cmin, __shfl_xor_sync(0xFFFFFFFFu, cmin, o));
        cmax = max(cmax, __shfl_xor_sync(0xFFFFFFFFu, cmax, o));
    }

    __shared__ int s[4][TB / 32];
    int wid = threadIdx.x >> 5, lid = threadIdx.x & 31;
    if (lid == 0) { s[0][wid] = rmin; s[1][wid] = rmax; s[2][wid] = cmin; s[3][wid] = cmax; }
    __syncthreads();
    if (threadIdx.x == 0) {
        #pragma unroll
        for (int i = 1; i < TB / 32; i++) {
            rmin = min(rmin, s[0][i]); rmax = max(rmax, s[1][i]);
            cmin = min(cmin, s[2][i]); cmax = max(cmax, s[3][i]);
        }
        g_part[blk][0] = rmin;
        g_part[blk][1] = rmax;
        g_part[blk][2] = cmin;
        g_part[blk][3] = cmax;
    }
}

// Inline replica of _axis_coords (float32 op order preserved).
// Handles the all-False-mask case: jnp.argmax on all-False gives (0, n-1).
__device__ __forceinline__ void axis_coords(int lo, int hi, int i,
                                            int& i0g, int& i1g, float& w) {
    if (hi < lo) { lo = 0; hi = H - 1; }   // H == W == 512
    float size = (float)(hi - lo);
    float src  = ((float)i + 0.5f) * size / (float)OUT - 0.5f;
    float mx   = fmaxf(size - 1.0f, 0.0f);
    src = fminf(fmaxf(src, 0.0f), mx);
    int   i0 = (int)floorf(src);
    int   i1 = min(i0 + 1, max(hi - lo - 1, 0));
    w = src - (float)i0;
    i0g = lo + i0;
    i1g = lo + i1;
}

// ---- 2D-tiled resize ----
#define TROW 16
#define TCOL 50
// Max source span per tile (scale <= 511/400 = 1.2775):
//   rows: 15*1.2775 + 2 -> <=22 ; cols: 49*1.2775 + 2 -> <=65
#define SROWS 24
#define SCOLS 68
#define SPITCH (SCOLS * C)          // 204 words; 204 % 32 = 12 -> conflict-safe
#define RZT 256

__global__ __launch_bounds__(RZT) void resize_kernel(const float* __restrict__ img,
                                                     float* __restrict__ out) {
    int tc0 = blockIdx.x * TCOL;   // first output col of tile (8 tiles)
    int tr0 = blockIdx.y * TROW;   // first output row of tile (25 tiles)
    int b   = blockIdx.z;          // batch

    __shared__ float src_s[SROWS * SPITCH];       // 19.6 KB
    __shared__ float obuf[TROW * TCOL * C];       // 9.6 KB
    __shared__ int   sb[4];

    // Reduce the 16 per-block bbox partials for this batch (warp 0).
    if (threadIdx.x < 32) {
        int rmin = INT_MAX, rmax = -1, cmin = INT_MAX, cmax = -1;
        if (threadIdx.x < BPB) {
            const int* p = g_part[b * BPB + threadIdx.x];
            rmin = p[0]; rmax = p[1]; cmin = p[2]; cmax = p[3];
        }
        #pragma unroll
        for (int o = 8; o > 0; o >>= 1) {
            rmin = min(rmin, __shfl_xor_sync(0xFFFFFFFFu, rmin, o));
            rmax = max(rmax, __shfl_xor_sync(0xFFFFFFFFu, rmax, o));
            cmin = min(cmin, __shfl_xor_sync(0xFFFFFFFFu, cmin, o));
            cmax = max(cmax, __shfl_xor_sync(0xFFFFFFFFu, cmax, o));
        }
        if (threadIdx.x == 0) {
            sb[0] = rmin; sb[1] = rmax; sb[2] = cmin; sb[3] = cmax;
        }
    }
    __syncthreads();

    int rlo = sb[0], rhi = sb[1], clo = sb[2], chi = sb[3];

    // Source span needed by this tile (i0 of first, i1 of last; monotone).
    int rs, re, cs, ce, t0, t1; float wt_;
    axis_coords(rlo, rhi, tr0,            rs, t1, wt_);
    axis_coords(rlo, rhi, tr0 + TROW - 1, t0, re, wt_);
    axis_coords(clo, chi, tc0,            cs, t1, wt_);
    axis_coords(clo, chi, tc0 + TCOL - 1, t0, ce, wt_);

    int nrows    = re - rs + 1;            // <= 22
    int rowwords = (ce - cs + 1) * C;      // <= 195

    // Stage source region (each global word read exactly once, coalesced).
    const float* gsrc = img + (((size_t)b * H + rs) * W + cs) * C;
    for (int rr = 0; rr < nrows; rr++) {
        const float* grow = gsrc + (size_t)rr * W * C;
        float* srow = src_s + rr * SPITCH;
        for (int w = threadIdx.x; w < rowwords; w += RZT)
            srow[w] = __ldg(grow + w);
    }
    __syncthreads();

    // Bilinear gather from smem.
    for (int px = threadIdx.x; px < TROW * TCOL; px += RZT) {
        int tr = px / TCOL;
        int tc = px - tr * TCOL;

        int r0, r1; float wr;
        axis_coords(rlo, rhi, tr0 + tr, r0, r1, wr);
        int c0, c1; float wc;
        axis_coords(clo, chi, tc0 + tc, c0, c1, wc);

        const float* p0 = src_s + (r0 - rs) * SPITCH;
        const float* p1 = src_s + (r1 - rs) * SPITCH;
        int o00 = (c0 - cs) * C, o01 = (c1 - cs) * C;

        float omwc = 1.0f - wc;
        float omwr = 1.0f - wr;
        float* o = obuf + px * C;   // stride-3 word addrs -> conflict-free
        #pragma unroll
        for (int ch = 0; ch < C; ch++) {
            float a00 = p0[o00 + ch];
            float a01 = p0[o01 + ch];
            float a10 = p1[o00 + ch];
            float a11 = p1[o01 + ch];
            float topv = a00 * omwc + a01 * wc;
            float botv = a10 * omwc + a11 * wc;
            o[ch] = topv * omwr + botv * wr;
        }
    }
    __syncthreads();

    // Coalesced writeback: each tile row is 150 contiguous words in gmem.
    const int RW = TCOL * C;   // 150
    for (int j = threadIdx.x; j < TROW * RW; j += RZT) {
        int tr = j / RW;
        int w  = j - tr * RW;
        out[(((size_t)b * OUT + tr0 + tr) * OUT + tc0) * C + w] = obuf[j];
    }
}

extern "C" void kernel_launch(void* const* d_in, const int* in_sizes, int n_in,
                              void* d_out, int out_size) {
    // Input-order detection: image has 25,165,824 elems, tensor 8,388,608.
    const float* image  = (const float*)d_in[0];
    const float* tensor = (const float*)d_in[1];
    if (n_in >= 2 && in_sizes[0] < in_sizes[1]) {
        image  = (const float*)d_in[1];
        tensor = (const float*)d_in[0];
    }
    float* out = (float*)d_out;

    bounds_kernel<<<NB * BPB, TB>>>(tensor);

    dim3 grid(OUT / TCOL, OUT / TROW, NB);   // 8 x 25 x 32
    resize_kernel<<<grid, RZT>>>(image, out);
}

// round 6
// speedup vs baseline: 1.4779x; 1.4779x over previous
#include <cuda_runtime.h>
#include <climits>

#define NB 32
#define H 512
#define W 512
#define C 3
#define OUT 400
#define THRESH 0.7f

#define BPB 16                      // bounds blocks per batch
#define ROWS_PER_BLK (H / BPB)      // 32
#define TB 256

// Per-block partial bbox: rmin, rmax, cmin, cmax. Plain-stored every launch.
__device__ int g_part[NB * BPB][4];

__global__ void bounds_kernel(const float* __restrict__ tensor) {
    int blk  = blockIdx.x;
    int b    = blk / BPB;
    int rb   = blk % BPB;
    int row0 = rb * ROWS_PER_BLK;

    const float4* base =
        (const float4*)(tensor + ((size_t)b * H + row0) * W);

    int rmin = INT_MAX, rmax = -1, cmin = INT_MAX, cmax = -1;

    const int NV = ROWS_PER_BLK * (W / 4);  // 4096 float4s
    for (int j = threadIdx.x; j < NV; j += TB) {
        float4 v = base[j];
        int r = j >> 7;
        int c = (j & 127) << 2;
        bool any = false;
        if (v.x > THRESH) { any = true; cmin = min(cmin, c    ); cmax = max(cmax, c    ); }
        if (v.y > THRESH) { any = true; cmin = min(cmin, c + 1); cmax = max(cmax, c + 1); }
        if (v.z > THRESH) { any = true; cmin = min(cmin, c + 2); cmax = max(cmax, c + 2); }
        if (v.w > THRESH) { any = true; cmin = min(cmin, c + 3); cmax = max(cmax, c + 3); }
        if (any) {
            int rr = row0 + r;
            rmin = min(rmin, rr);
            rmax = max(rmax, rr);
        }
    }

    #pragma unroll
    for (int o = 16; o > 0; o >>= 1) {
        rmin = min(rmin, __shfl_xor_sync(0xFFFFFFFFu, rmin, o));
        rmax = max(rmax, __shfl_xor_sync(0xFFFFFFFFu, rmax, o));
        cmin = min(cmin, __shfl_xor_sync(0xFFFFFFFFu, cmin, o));
        cmax = max(cmax, __shfl_xor_sync(0xFFFFFFFFu, cmax, o));
    }

    __shared__ int s[4][TB / 32];
    int wid = threadIdx.x >> 5, lid = threadIdx.x & 31;
    if (lid == 0) { s[0][wid] = rmin; s[1][wid] = rmax; s[2][wid] = cmin; s[3][wid] = cmax; }
    __syncthreads();
    if (threadIdx.x == 0) {
        #pragma unroll
        for (int i = 1; i < TB / 32; i++) {
            rmin = min(rmin, s[0][i]); rmax = max(rmax, s[1][i]);
            cmin = min(cmin, s[2][i]); cmax = max(cmax, s[3][i]);
        }
        g_part[blk][0] = rmin;
        g_part[blk][1] = rmax;
        g_part[blk][2] = cmin;
        g_part[blk][3] = cmax;
    }
}

// Inline replica of _axis_coords (float32 op order preserved).
// Handles the all-False-mask case: jnp.argmax on all-False gives (0, n-1).
__device__ __forceinline__ void axis_coords(int lo, int hi, int i,
                                            int& i0g, int& i1g, float& w) {
    if (hi < lo) { lo = 0; hi = H - 1; }   // H == W == 512
    float size = (float)(hi - lo);
    float src  = ((float)i + 0.5f) * size / (float)OUT - 0.5f;
    float mx   = fmaxf(size - 1.0f, 0.0f);
    src = fminf(fmaxf(src, 0.0f), mx);
    int   i0 = (int)floorf(src);
    int   i1 = min(i0 + 1, max(hi - lo - 1, 0));
    w = src - (float)i0;
    i0g = lo + i0;
    i1g = lo + i1;
}

#define RZT 256
#define ELEMS_PER_BATCH (OUT * OUT * C)          // 480000
#define BLOCKS_PER_BATCH (ELEMS_PER_BATCH / RZT) // 1875 exact

// One thread per output ELEMENT (b, r, c, ch). Within a warp, consecutive
// elements cover ~10.7 output pixels -> each of the 4 gather LDGs has a
// ~164-byte warp footprint (~2 lines), and the store is fully contiguous.
__global__ __launch_bounds__(RZT) void resize_kernel(const float* __restrict__ img,
                                                     float* __restrict__ out) {
    int b = blockIdx.x / BLOCKS_PER_BATCH;
    __shared__ int sb[4];

    // Reduce the 16 per-block bbox partials for this batch (warp 0).
    if (threadIdx.x < 32) {
        int rmin = INT_MAX, rmax = -1, cmin = INT_MAX, cmax = -1;
        if (threadIdx.x < BPB) {
            const int* p = g_part[b * BPB + threadIdx.x];
            rmin = p[0]; rmax = p[1]; cmin = p[2]; cmax = p[3];
        }
        #pragma unroll
        for (int o = 8; o > 0; o >>= 1) {
            rmin = min(rmin, __shfl_xor_sync(0xFFFFFFFFu, rmin, o));
            rmax = max(rmax, __shfl_xor_sync(0xFFFFFFFFu, rmax, o));
            cmin = min(cmin, __shfl_xor_sync(0xFFFFFFFFu, cmin, o));
            cmax = max(cmax, __shfl_xor_sync(0xFFFFFFFFu, cmax, o));
        }
        if (threadIdx.x == 0) {
            sb[0] = rmin; sb[1] = rmax; sb[2] = cmin; sb[3] = cmax;
        }
    }
    __syncthreads();

    int rlo = sb[0], rhi = sb[1], clo = sb[2], chi = sb[3];

    // Element index within this batch.
    int eb = (blockIdx.x - b * BLOCKS_PER_BATCH) * RZT + threadIdx.x;
    int ch = eb % C;
    int px = eb / C;
    int c  = px % OUT;
    int r  = px / OUT;

    int r0, r1; float wr;
    axis_coords(rlo, rhi, r, r0, r1, wr);
    int c0, c1; float wc;
    axis_coords(clo, chi, c, c0, c1, wc);

    const float* base = img + (size_t)b * (H * W * C);
    int row0 = r0 * (W * C), row1 = r1 * (W * C);
    int col0 = c0 * C + ch,  col1 = c1 * C + ch;

    float a00 = __ldg(base + row0 + col0);
    float a01 = __ldg(base + row0 + col1);
    float a10 = __ldg(base + row1 + col0);
    float a11 = __ldg(base + row1 + col1);

    float omwc = 1.0f - wc;
    float omwr = 1.0f - wr;
    float topv = a00 * omwc + a01 * wc;
    float botv = a10 * omwc + a11 * wc;

    out[(size_t)b * ELEMS_PER_BATCH + eb] = topv * omwr + botv * wr;
}

extern "C" void kernel_launch(void* const* d_in, const int* in_sizes, int n_in,
                              void* d_out, int out_size) {
    // Input-order detection: image has 25,165,824 elems, tensor 8,388,608.
    const float* image  = (const float*)d_in[0];
    const float* tensor = (const float*)d_in[1];
    if (n_in >= 2 && in_sizes[0] < in_sizes[1]) {
        image  = (const float*)d_in[1];
        tensor = (const float*)d_in[0];
    }
    float* out = (float*)d_out;

    bounds_kernel<<<NB * BPB, TB>>>(tensor);
    resize_kernel<<<NB * BLOCKS_PER_BATCH, RZT>>>(image, out);
}

// round 7
// speedup vs baseline: 1.6491x; 1.1159x over previous
#include <cuda_runtime.h>
#include <climits>

#define NB 32
#define H 512
#define W 512
#define C 3
#define OUT 400
#define THRESH 0.7f

#define BPB 16                      // bounds blocks per batch
#define ROWS_PER_BLK (H / BPB)      // 32
#define TB 256

// Per-block partial bbox: rmin, rmax, cmin, cmax. Plain-stored every launch.
__device__ int g_part[NB * BPB][4];
// Precomputed axis coords: x=i0, y=i1, z=bits(w).
__device__ int4 g_rcoord[NB][OUT];
__device__ int4 g_ccoord[NB][OUT];

__global__ void bounds_kernel(const float* __restrict__ tensor) {
    int blk  = blockIdx.x;
    int b    = blk / BPB;
    int rb   = blk % BPB;
    int row0 = rb * ROWS_PER_BLK;

    const float4* base =
        (const float4*)(tensor + ((size_t)b * H + row0) * W);

    int rmin = INT_MAX, rmax = -1, cmin = INT_MAX, cmax = -1;

    const int NV = ROWS_PER_BLK * (W / 4);  // 4096 float4s
    for (int j = threadIdx.x; j < NV; j += TB) {
        float4 v = base[j];
        int r = j >> 7;
        int c = (j & 127) << 2;
        bool any = false;
        if (v.x > THRESH) { any = true; cmin = min(cmin, c    ); cmax = max(cmax, c    ); }
        if (v.y > THRESH) { any = true; cmin = min(cmin, c + 1); cmax = max(cmax, c + 1); }
        if (v.z > THRESH) { any = true; cmin = min(cmin, c + 2); cmax = max(cmax, c + 2); }
        if (v.w > THRESH) { any = true; cmin = min(cmin, c + 3); cmax = max(cmax, c + 3); }
        if (any) {
            int rr = row0 + r;
            rmin = min(rmin, rr);
            rmax = max(rmax, rr);
        }
    }

    #pragma unroll
    for (int o = 16; o > 0; o >>= 1) {
        rmin = min(rmin, __shfl_xor_sync(0xFFFFFFFFu, rmin, o));
        rmax = max(rmax, __shfl_xor_sync(0xFFFFFFFFu, rmax, o));
        cmin = min(cmin, __shfl_xor_sync(0xFFFFFFFFu, cmin, o));
        cmax = max(cmax, __shfl_xor_sync(0xFFFFFFFFu, cmax, o));
    }

    __shared__ int s[4][TB / 32];
    int wid = threadIdx.x >> 5, lid = threadIdx.x & 31;
    if (lid == 0) { s[0][wid] = rmin; s[1][wid] = rmax; s[2][wid] = cmin; s[3][wid] = cmax; }
    __syncthreads();
    if (threadIdx.x == 0) {
        #pragma unroll
        for (int i = 1; i < TB / 32; i++) {
            rmin = min(rmin, s[0][i]); rmax = max(rmax, s[1][i]);
            cmin = min(cmin, s[2][i]); cmax = max(cmax, s[3][i]);
        }
        g_part[blk][0] = rmin;
        g_part[blk][1] = rmax;
        g_part[blk][2] = cmin;
        g_part[blk][3] = cmax;
    }
}

// Inline replica of _axis_coords (float32 op order preserved).
// Handles the all-False-mask case: jnp.argmax on all-False gives (0, n-1).
__device__ __forceinline__ void axis_coords(int lo, int hi, int i,
                                            int& i0g, int& i1g, float& w) {
    if (hi < lo) { lo = 0; hi = H - 1; }   // H == W == 512
    float size = (float)(hi - lo);
    float src  = ((float)i + 0.5f) * size / (float)OUT - 0.5f;
    float mx   = fmaxf(size - 1.0f, 0.0f);
    src = fminf(fmaxf(src, 0.0f), mx);
    int   i0 = (int)floorf(src);
    int   i1 = min(i0 + 1, max(hi - lo - 1, 0));
    w = src - (float)i0;
    i0g = lo + i0;
    i1g = lo + i1;
}

// One block per batch: reduce bbox partials, then fill both coord tables.
__global__ __launch_bounds__(256) void coords_kernel() {
    int b = blockIdx.x;
    __shared__ int sb[4];

    if (threadIdx.x < 32) {
        int rmin = INT_MAX, rmax = -1, cmin = INT_MAX, cmax = -1;
        if (threadIdx.x < BPB) {
            const int* p = g_part[b * BPB + threadIdx.x];
            rmin = p[0]; rmax = p[1]; cmin = p[2]; cmax = p[3];
        }
        #pragma unroll
        for (int o = 8; o > 0; o >>= 1) {
            rmin = min(rmin, __shfl_xor_sync(0xFFFFFFFFu, rmin, o));
            rmax = max(rmax, __shfl_xor_sync(0xFFFFFFFFu, rmax, o));
            cmin = min(cmin, __shfl_xor_sync(0xFFFFFFFFu, cmin, o));
            cmax = max(cmax, __shfl_xor_sync(0xFFFFFFFFu, cmax, o));
        }
        if (threadIdx.x == 0) {
            sb[0] = rmin; sb[1] = rmax; sb[2] = cmin; sb[3] = cmax;
        }
    }
    __syncthreads();

    int rlo = sb[0], rhi = sb[1], clo = sb[2], chi = sb[3];

    for (int t = threadIdx.x; t < 2 * OUT; t += 256) {
        int axis = t / OUT;
        int i    = t - axis * OUT;
        int i0, i1; float w;
        if (axis == 0) {
            axis_coords(rlo, rhi, i, i0, i1, w);
            g_rcoord[b][i] = make_int4(i0, i1, __float_as_int(w), 0);
        } else {
            axis_coords(clo, chi, i, i0, i1, w);
            g_ccoord[b][i] = make_int4(i0, i1, __float_as_int(w), 0);
        }
    }
}

#define RZT 256
#define ELEMS_PER_BATCH (OUT * OUT * C)          // 480000
#define BLOCKS_PER_BATCH (ELEMS_PER_BATCH / RZT) // 1875 exact

// One thread per output ELEMENT (b, r, c, ch). Coords come from tables
// (row entry warp-uniform -> broadcast; col entries coalesced). 4 gather
// LDGs with ~2-line warp footprints; contiguous STG.
__global__ __launch_bounds__(RZT) void resize_kernel(const float* __restrict__ img,
                                                     float* __restrict__ out) {
    int b  = blockIdx.y;
    int eb = blockIdx.x * RZT + threadIdx.x;

    int ch = eb % C;
    int px = eb / C;
    int c  = px % OUT;
    int r  = px / OUT;

    int4 rc = g_rcoord[b][r];
    int4 cc = g_ccoord[b][c];
    float wr = __int_as_float(rc.z);
    float wc = __int_as_float(cc.z);

    const float* base = img + (size_t)b * (H * W * C);
    int row0 = rc.x * (W * C), row1 = rc.y * (W * C);
    int col0 = cc.x * C + ch,  col1 = cc.y * C + ch;

    float a00 = __ldg(base + row0 + col0);
    float a01 = __ldg(base + row0 + col1);
    float a10 = __ldg(base + row1 + col0);
    float a11 = __ldg(base + row1 + col1);

    float omwc = 1.0f - wc;
    float omwr = 1.0f - wr;
    float topv = a00 * omwc + a01 * wc;
    float botv = a10 * omwc + a11 * wc;

    out[(size_t)b * ELEMS_PER_BATCH + eb] = topv * omwr + botv * wr;
}

extern "C" void kernel_launch(void* const* d_in, const int* in_sizes, int n_in,
                              void* d_out, int out_size) {
    // Input-order detection: image has 25,165,824 elems, tensor 8,388,608.
    const float* image  = (const float*)d_in[0];
    const float* tensor = (const float*)d_in[1];
    if (n_in >= 2 && in_sizes[0] < in_sizes[1]) {
        image  = (const float*)d_in[1];
        tensor = (const float*)d_in[0];
    }
    float* out = (float*)d_out;

    bounds_kernel<<<NB * BPB, TB>>>(tensor);
    coords_kernel<<<NB, 256>>>();

    dim3 grid(BLOCKS_PER_BATCH, NB);
    resize_kernel<<<grid, RZT>>>(image, out);
}

// round 8
// speedup vs baseline: 2.0562x; 1.2468x over previous
#include <cuda_runtime.h>
#include <climits>

#define NB 32
#define H 512
#define W 512
#define C 3
#define OUT 400
#define THRESH 0.7f

#define BPB 32                      // bounds blocks per batch
#define ROWS_PER_BLK (H / BPB)      // 16
#define TB 256

// Per-block partial bbox: rmin, rmax, cmin, cmax. Plain-stored every launch.
__device__ int g_part[NB * BPB][4];
// Precomputed axis coords: x=i0, y=i1, z=bits(w).
__device__ int4 g_rcoord[NB][OUT];
__device__ int4 g_ccoord[NB][OUT];

__global__ void bounds_kernel(const float* __restrict__ tensor) {
    int blk  = blockIdx.x;
    int b    = blk / BPB;
    int rb   = blk % BPB;
    int row0 = rb * ROWS_PER_BLK;

    const float4* base =
        (const float4*)(tensor + ((size_t)b * H + row0) * W);

    int rmin = INT_MAX, rmax = -1, cmin = INT_MAX, cmax = -1;

    const int NV = ROWS_PER_BLK * (W / 4);  // 16*128 = 2048 float4s
    #pragma unroll 4
    for (int j = threadIdx.x; j < NV; j += TB) {
        float4 v = base[j];
        int r = j >> 7;
        int c = (j & 127) << 2;
        bool any = false;
        if (v.x > THRESH) { any = true; cmin = min(cmin, c    ); cmax = max(cmax, c    ); }
        if (v.y > THRESH) { any = true; cmin = min(cmin, c + 1); cmax = max(cmax, c + 1); }
        if (v.z > THRESH) { any = true; cmin = min(cmin, c + 2); cmax = max(cmax, c + 2); }
        if (v.w > THRESH) { any = true; cmin = min(cmin, c + 3); cmax = max(cmax, c + 3); }
        if (any) {
            int rr = row0 + r;
            rmin = min(rmin, rr);
            rmax = max(rmax, rr);
        }
    }

    #pragma unroll
    for (int o = 16; o > 0; o >>= 1) {
        rmin = min(rmin, __shfl_xor_sync(0xFFFFFFFFu, rmin, o));
        rmax = max(rmax, __shfl_xor_sync(0xFFFFFFFFu, rmax, o));
        cmin = min(cmin, __shfl_xor_sync(0xFFFFFFFFu, cmin, o));
        cmax = max(cmax, __shfl_xor_sync(0xFFFFFFFFu, cmax, o));
    }

    __shared__ int s[4][TB / 32];
    int wid = threadIdx.x >> 5, lid = threadIdx.x & 31;
    if (lid == 0) { s[0][wid] = rmin; s[1][wid] = rmax; s[2][wid] = cmin; s[3][wid] = cmax; }
    __syncthreads();
    if (threadIdx.x == 0) {
        #pragma unroll
        for (int i = 1; i < TB / 32; i++) {
            rmin = min(rmin, s[0][i]); rmax = max(rmax, s[1][i]);
            cmin = min(cmin, s[2][i]); cmax = max(cmax, s[3][i]);
        }
        g_part[blk][0] = rmin;
        g_part[blk][1] = rmax;
        g_part[blk][2] = cmin;
        g_part[blk][3] = cmax;
    }
}

// Inline replica of _axis_coords (float32 op order preserved).
// Handles the all-False-mask case: jnp.argmax on all-False gives (0, n-1).
__device__ __forceinline__ void axis_coords(int lo, int hi, int i,
                                            int& i0g, int& i1g, float& w) {
    if (hi < lo) { lo = 0; hi = H - 1; }   // H == W == 512
    float size = (float)(hi - lo);
    float src  = ((float)i + 0.5f) * size / (float)OUT - 0.5f;
    float mx   = fmaxf(size - 1.0f, 0.0f);
    src = fminf(fmaxf(src, 0.0f), mx);
    int   i0 = (int)floorf(src);
    int   i1 = min(i0 + 1, max(hi - lo - 1, 0));
    w = src - (float)i0;
    i0g = lo + i0;
    i1g = lo + i1;
}

// One block per batch: reduce bbox partials, then fill both coord tables.
__global__ __launch_bounds__(256) void coords_kernel() {
    int b = blockIdx.x;
    __shared__ int sb[4];

    if (threadIdx.x < 32) {
        const int* p = g_part[b * BPB + threadIdx.x];   // BPB == 32
        int rmin = p[0], rmax = p[1], cmin = p[2], cmax = p[3];
        #pragma unroll
        for (int o = 16; o > 0; o >>= 1) {
            rmin = min(rmin, __shfl_xor_sync(0xFFFFFFFFu, rmin, o));
            rmax = max(rmax, __shfl_xor_sync(0xFFFFFFFFu, rmax, o));
            cmin = min(cmin, __shfl_xor_sync(0xFFFFFFFFu, cmin, o));
            cmax = max(cmax, __shfl_xor_sync(0xFFFFFFFFu, cmax, o));
        }
        if (threadIdx.x == 0) {
            sb[0] = rmin; sb[1] = rmax; sb[2] = cmin; sb[3] = cmax;
        }
    }
    __syncthreads();

    int rlo = sb[0], rhi = sb[1], clo = sb[2], chi = sb[3];

    for (int t = threadIdx.x; t < 2 * OUT; t += 256) {
        int axis = t / OUT;
        int i    = t - axis * OUT;
        int i0, i1; float w;
        if (axis == 0) {
            axis_coords(rlo, rhi, i, i0, i1, w);
            g_rcoord[b][i] = make_int4(i0, i1, __float_as_int(w), 0);
        } else {
            axis_coords(clo, chi, i, i0, i1, w);
            g_ccoord[b][i] = make_int4(i0, i1, __float_as_int(w), 0);
        }
    }
}

#define RZT 256
#define ELEMS_PER_BATCH (OUT * OUT * C)            // 480000
#define TOTAL_ELEMS (NB * ELEMS_PER_BATCH)         // 15,360,000
#define RZ_BLOCKS 1184                             // ~1 wave on 148 SMs

// Persistent grid-stride kernel, one output ELEMENT per loop step.
// Coords from tables (row entry warp-uniform; col entries coalesced).
// 4 gather LDGs per element with ~2-line warp footprints; contiguous STG.
__global__ __launch_bounds__(RZT) void resize_kernel(const float* __restrict__ img,
                                                     float* __restrict__ out) {
    int stride = RZ_BLOCKS * RZT;
    #pragma unroll 2
    for (int idx = blockIdx.x * RZT + threadIdx.x; idx < TOTAL_ELEMS; idx += stride) {
        int b  = idx / ELEMS_PER_BATCH;
        int eb = idx - b * ELEMS_PER_BATCH;
        int ch = eb % C;
        int px = eb / C;
        int c  = px % OUT;
        int r  = px / OUT;

        int4 rc = g_rcoord[b][r];
        int4 cc = g_ccoord[b][c];
        float wr = __int_as_float(rc.z);
        float wc = __int_as_float(cc.z);

        const float* base = img + (size_t)b * (H * W * C);
        int row0 = rc.x * (W * C), row1 = rc.y * (W * C);
        int col0 = cc.x * C + ch,  col1 = cc.y * C + ch;

        float a00 = __ldg(base + row0 + col0);
        float a01 = __ldg(base + row0 + col1);
        float a10 = __ldg(base + row1 + col0);
        float a11 = __ldg(base + row1 + col1);

        float omwc = 1.0f - wc;
        float omwr = 1.0f - wr;
        float topv = a00 * omwc + a01 * wc;
        float botv = a10 * omwc + a11 * wc;

        out[idx] = topv * omwr + botv * wr;
    }
}

extern "C" void kernel_launch(void* const* d_in, const int* in_sizes, int n_in,
                              void* d_out, int out_size) {
    // Input-order detection: image has 25,165,824 elems, tensor 8,388,608.
    const float* image  = (const float*)d_in[0];
    const float* tensor = (const float*)d_in[1];
    if (n_in >= 2 && in_sizes[0] < in_sizes[1]) {
        image  = (const float*)d_in[1];
        tensor = (const float*)d_in[0];
    }
    float* out = (float*)d_out;

    bounds_kernel<<<NB * BPB, TB>>>(tensor);
    coords_kernel<<<NB, 256>>>();
    resize_kernel<<<RZ_BLOCKS, RZT>>>(image, out);
}

// round 9
// speedup vs baseline: 2.5335x; 1.2321x over previous
#include <cuda_runtime.h>
#include <climits>

#define NB 32
#define H 512
#define W 512
#define C 3
#define OUT 400
#define THRESH 0.7f

#define BPB 32                      // bounds blocks per batch
#define ROWS_PER_BLK (H / BPB)      // 16
#define TB 256

// Per-block partial bbox: rmin, rmax, cmin, cmax. Plain-stored every launch.
__device__ int g_part[NB * BPB][4];

__global__ void bounds_kernel(const float* __restrict__ tensor) {
    int blk  = blockIdx.x;
    int b    = blk / BPB;
    int rb   = blk % BPB;
    int row0 = rb * ROWS_PER_BLK;

    const float4* base =
        (const float4*)(tensor + ((size_t)b * H + row0) * W);

    // Front-batched loads: 8 independent LDG.128 per thread (MLP=8).
    float4 v[8];
    #pragma unroll
    for (int k = 0; k < 8; k++)
        v[k] = base[threadIdx.x + k * TB];

    int rmin = INT_MAX, rmax = -1, cmin = INT_MAX, cmax = -1;

    #pragma unroll
    for (int k = 0; k < 8; k++) {
        int j = threadIdx.x + k * TB;
        int r = j >> 7;            // j / 128 rows of 128 float4s
        int c = (j & 127) << 2;
        bool any = false;
        if (v[k].x > THRESH) { any = true; cmin = min(cmin, c    ); cmax = max(cmax, c    ); }
        if (v[k].y > THRESH) { any = true; cmin = min(cmin, c + 1); cmax = max(cmax, c + 1); }
        if (v[k].z > THRESH) { any = true; cmin = min(cmin, c + 2); cmax = max(cmax, c + 2); }
        if (v[k].w > THRESH) { any = true; cmin = min(cmin, c + 3); cmax = max(cmax, c + 3); }
        if (any) {
            int rr = row0 + r;
            rmin = min(rmin, rr);
            rmax = max(rmax, rr);
        }
    }

    #pragma unroll
    for (int o = 16; o > 0; o >>= 1) {
        rmin = min(rmin, __shfl_xor_sync(0xFFFFFFFFu, rmin, o));
        rmax = max(rmax, __shfl_xor_sync(0xFFFFFFFFu, rmax, o));
        cmin = min(cmin, __shfl_xor_sync(0xFFFFFFFFu, cmin, o));
        cmax = max(cmax, __shfl_xor_sync(0xFFFFFFFFu, cmax, o));
    }

    __shared__ int s[4][TB / 32];
    int wid = threadIdx.x >> 5, lid = threadIdx.x & 31;
    if (lid == 0) { s[0][wid] = rmin; s[1][wid] = rmax; s[2][wid] = cmin; s[3][wid] = cmax; }
    __syncthreads();
    if (threadIdx.x == 0) {
        #pragma unroll
        for (int i = 1; i < TB / 32; i++) {
            rmin = min(rmin, s[0][i]); rmax = max(rmax, s[1][i]);
            cmin = min(cmin, s[2][i]); cmax = max(cmax, s[3][i]);
        }
        g_part[blk][0] = rmin;
        g_part[blk][1] = rmax;
        g_part[blk][2] = cmin;
        g_part[blk][3] = cmax;
    }
}

// Inline replica of _axis_coords (float32 op order preserved).
// Handles the all-False-mask case: jnp.argmax on all-False gives (0, n-1).
__device__ __forceinline__ void axis_coords(int lo, int hi, int i,
                                            int& i0g, int& i1g, float& w) {
    if (hi < lo) { lo = 0; hi = H - 1; }   // H == W == 512
    float size = (float)(hi - lo);
    float src  = ((float)i + 0.5f) * size / (float)OUT - 0.5f;
    float mx   = fmaxf(size - 1.0f, 0.0f);
    src = fminf(fmaxf(src, 0.0f), mx);
    int   i0 = (int)floorf(src);
    int   i1 = min(i0 + 1, max(hi - lo - 1, 0));
    w = src - (float)i0;
    i0g = lo + i0;
    i1g = lo + i1;
}

// ---- Resize: 37 blocks per batch, each owns 10-11 output rows ----
#define SUBS 37                       // 32*37 = 1184 blocks (~1 wave)
#define RZT 256
#define ROWWORDS (OUT * C)            // 1200

__global__ __launch_bounds__(RZT) void resize_kernel(const float* __restrict__ img,
                                                     float* __restrict__ out) {
    int b   = blockIdx.x / SUBS;
    int sub = blockIdx.x - b * SUBS;
    int row_start = sub * 10 + min(sub, 30);   // first 30 subs get 11 rows
    int nrows     = 10 + (sub < 30 ? 1 : 0);

    __shared__ int   sb[4];
    __shared__ int   sc0[OUT];
    __shared__ int   sc1[OUT];
    __shared__ float swc[OUT];

    // Reduce the 32 per-block bbox partials for this batch (warp 0).
    if (threadIdx.x < 32) {
        const int* p = g_part[b * BPB + threadIdx.x];
        int rmin = p[0], rmax = p[1], cmin = p[2], cmax = p[3];
        #pragma unroll
        for (int o = 16; o > 0; o >>= 1) {
            rmin = min(rmin, __shfl_xor_sync(0xFFFFFFFFu, rmin, o));
            rmax = max(rmax, __shfl_xor_sync(0xFFFFFFFFu, rmax, o));
            cmin = min(cmin, __shfl_xor_sync(0xFFFFFFFFu, cmin, o));
            cmax = max(cmax, __shfl_xor_sync(0xFFFFFFFFu, cmax, o));
        }
        if (threadIdx.x == 0) {
            sb[0] = rmin; sb[1] = rmax; sb[2] = cmin; sb[3] = cmax;
        }
    }
    __syncthreads();

    int rlo = sb[0], rhi = sb[1], clo = sb[2], chi = sb[3];

    // Column coord table in shared memory (built once per block).
    for (int i = threadIdx.x; i < OUT; i += RZT) {
        int c0, c1; float w;
        axis_coords(clo, chi, i, c0, c1, w);
        sc0[i] = c0 * C;
        sc1[i] = c1 * C;
        swc[i] = w;
    }
    __syncthreads();

    const float* bimg = img + (size_t)b * (H * W * C);

    for (int rr = 0; rr < nrows; rr++) {
        int r = row_start + rr;
        int r0, r1; float wr;
        axis_coords(rlo, rhi, r, r0, r1, wr);   // uniform across block
        float omwr = 1.0f - wr;

        const float* p0 = bimg + r0 * (W * C);
        const float* p1 = bimg + r1 * (W * C);
        float* orow = out + ((size_t)b * OUT + r) * ROWWORDS;

        // 1200 elements, 5 unrolled strides -> up to 20 independent LDGs.
        #pragma unroll
        for (int it = 0; it < 5; it++) {
            int e = it * RZT + threadIdx.x;
            if (it < 4 || e < ROWWORDS) {
                int c  = e / 3;
                int ch = e - c * 3;
                int o0 = sc0[c] + ch;
                int o1 = sc1[c] + ch;
                float wc = swc[c];

                float a00 = __ldg(p0 + o0);
                float a01 = __ldg(p0 + o1);
                float a10 = __ldg(p1 + o0);
                float a11 = __ldg(p1 + o1);

                float omwc = 1.0f - wc;
                float topv = a00 * omwc + a01 * wc;
                float botv = a10 * omwc + a11 * wc;
                orow[e] = topv * omwr + botv * wr;
            }
        }
    }
}

extern "C" void kernel_launch(void* const* d_in, const int* in_sizes, int n_in,
                              void* d_out, int out_size) {
    // Input-order detection: image has 25,165,824 elems, tensor 8,388,608.
    const float* image  = (const float*)d_in[0];
    const float* tensor = (const float*)d_in[1];
    if (n_in >= 2 && in_sizes[0] < in_sizes[1]) {
        image  = (const float*)d_in[1];
        tensor = (const float*)d_in[0];
    }
    float* out = (float*)d_out;

    bounds_kernel<<<NB * BPB, TB>>>(tensor);
    resize_kernel<<<NB * SUBS, RZT>>>(image, out);
}